// round 1
// baseline (speedup 1.0000x reference)
#include <cuda_runtime.h>
#include <cuda_bf16.h>
#include <cstdint>

// LSTM: B=2048, T=512, F=64, H=16 (4H=64 gate columns), then MLP 16->8->4->1.
// One warp per batch element. Lane l owns gate columns l and l+32.
// Dot products packed over k with fma.rn.f32x2 (Blackwell f32x2 pipe, 2 FLOP/issue).

#define ULL unsigned long long

static constexpr int Bsz = 2048;
static constexpr int T   = 512;
static constexpr int F   = 64;
static constexpr int H   = 16;
static constexpr int G   = 64;   // 4*H

__device__ __forceinline__ ULL f2pack(float lo, float hi) {
    ULL r;
    asm("mov.b64 %0, {%1, %2};" : "=l"(r) : "f"(lo), "f"(hi));
    return r;
}
__device__ __forceinline__ void f2unpack(ULL v, float& lo, float& hi) {
    asm("mov.b64 {%0, %1}, %2;" : "=f"(lo), "=f"(hi) : "l"(v));
}
__device__ __forceinline__ ULL ffma2(ULL a, ULL b, ULL c) {
    ULL d;
    asm("fma.rn.f32x2 %0, %1, %2, %3;" : "=l"(d) : "l"(a), "l"(b), "l"(c));
    return d;
}
__device__ __forceinline__ float fast_sigmoid(float x) {
    // 1/(1+exp(-x)) via fast intrinsics (MUFU.EX2 + MUFU.RCP); ~1e-6 rel err.
    return __fdividef(1.0f, 1.0f + __expf(-x));
}

__global__ void __launch_bounds__(128)
lstm_fused_kernel(const float* __restrict__ x,
                  const float* __restrict__ Wx,   // [64, 64] row-major (f, g)
                  const float* __restrict__ Wh,   // [16, 64]
                  const float* __restrict__ bias, // [64]
                  const float* __restrict__ W2,   // [16, 8]
                  const float* __restrict__ b2,   // [8]
                  const float* __restrict__ W3,   // [8, 4]
                  const float* __restrict__ b3,   // [4]
                  const float* __restrict__ Wo,   // [4, 1]
                  const float* __restrict__ bo,   // [1]
                  float* __restrict__ out)        // [B]
{
    const int lane = threadIdx.x & 31;
    const int w    = threadIdx.x >> 5;            // warp index within block (0..3)
    const int batch = blockIdx.x * 4 + w;
    if (batch >= Bsz) return;

    // ---- per-warp shared staging ----
    __shared__ ULL sx2[4][32];   // 64 x-values as 32 packed pairs per warp
    __shared__ ULL sh2[4][8];    // 16 h-values as 8 packed pairs per warp

    // ---- weight pairs (over k) held in registers ----
    // wxa[kk] = (Wx[2kk][l], Wx[2kk+1][l]); wxb same for column l+32.
    ULL wxa[32], wxb[32], wha[8], whb[8];
#pragma unroll
    for (int kk = 0; kk < 32; kk++) {
        wxa[kk] = f2pack(__ldg(&Wx[(2 * kk) * G + lane]),
                         __ldg(&Wx[(2 * kk + 1) * G + lane]));
        wxb[kk] = f2pack(__ldg(&Wx[(2 * kk) * G + lane + 32]),
                         __ldg(&Wx[(2 * kk + 1) * G + lane + 32]));
    }
#pragma unroll
    for (int kk = 0; kk < 8; kk++) {
        wha[kk] = f2pack(__ldg(&Wh[(2 * kk) * G + lane]),
                         __ldg(&Wh[(2 * kk + 1) * G + lane]));
        whb[kk] = f2pack(__ldg(&Wh[(2 * kk) * G + lane + 32]),
                         __ldg(&Wh[(2 * kk + 1) * G + lane + 32]));
    }
    const float bA = __ldg(&bias[lane]);
    const float bB = __ldg(&bias[lane + 32]);

    // init h = 0 in shared, c = 0 in register
    if (lane < 16) ((float*)sh2[w])[lane] = 0.0f;
    float c_state = 0.0f;

    // x stream: each lane reads float2 (x[t][2l], x[t][2l+1]); stride 32 float2 per step.
    const float2* xrow = reinterpret_cast<const float2*>(x + (size_t)batch * T * F) + lane;
    float2 xc = __ldg(xrow);            // t = 0
    float2 xn = __ldg(xrow + 32);       // t = 1

    for (int t = 0; t < T; t++) {
        // stage x_t into shared (pairs are then lane-uniform broadcasts)
        *reinterpret_cast<float2*>(&sx2[w][lane]) = xc;
        __syncwarp();

        // distance-2 prefetch
        int tp = (t + 2 < T) ? (t + 2) : (T - 1);
        float2 xf = __ldg(xrow + tp * 32);

        ULL acc_a = 0ULL, acc_b = 0ULL;   // bit pattern of (0.f, 0.f)
#pragma unroll
        for (int kk = 0; kk < 32; kk++) {
            ULL p = sx2[w][kk];
            acc_a = ffma2(p, wxa[kk], acc_a);
            acc_b = ffma2(p, wxb[kk], acc_b);
        }
#pragma unroll
        for (int kk = 0; kk < 8; kk++) {
            ULL p = sh2[w][kk];
            acc_a = ffma2(p, wha[kk], acc_a);
            acc_b = ffma2(p, whb[kk], acc_b);
        }

        float a0, a1, c0, c1;
        f2unpack(acc_a, a0, a1);
        f2unpack(acc_b, c0, c1);
        float za = a0 + a1 + bA;          // lane<16: i-gate preact; lane>=16: f-gate
        float zb = c0 + c1 + bB;          // lane<16: g candidate;   lane>=16: o-gate

        float v1 = fast_sigmoid(za);                                  // i or f
        float v2 = (lane < 16) ? fmaxf(zb, 0.0f) : fast_sigmoid(zb);  // g or o

        float fpart = __shfl_xor_sync(0xFFFFFFFFu, v1, 16);  // lane<16 receives f
        float opart = __shfl_xor_sync(0xFFFFFFFFu, v2, 16);  // lane<16 receives o

        c_state = fpart * c_state + v1 * v2;     // f*c + i*g  (valid on lanes 0..15)
        float hnew = opart * fmaxf(c_state, 0.0f);
        if (lane < 16) ((float*)sh2[w])[lane] = hnew;
        // visibility of h-store to other lanes is guaranteed by the
        // __syncwarp() at the top of the next iteration.

        xc = xn;
        xn = xf;
    }
    __syncwarp();

    // ---- MLP head: lane 0 per warp ----
    if (lane == 0) {
        const float* hT = (const float*)sh2[w];
        float x2v[8];
#pragma unroll
        for (int u = 0; u < 8; u++) {
            float s = __ldg(&b2[u]);
#pragma unroll
            for (int j = 0; j < 16; j++) s += hT[j] * __ldg(&W2[j * 8 + u]);
            x2v[u] = fmaxf(s, 0.0f);
        }
        float x3v[4];
#pragma unroll
        for (int u = 0; u < 4; u++) {
            float s = __ldg(&b3[u]);
#pragma unroll
            for (int j = 0; j < 8; j++) s += x2v[j] * __ldg(&W3[j * 4 + u]);
            x3v[u] = fmaxf(s, 0.0f);
        }
        float s = __ldg(&bo[0]);
#pragma unroll
        for (int u = 0; u < 4; u++) s += x3v[u] * __ldg(&Wo[u]);
        out[batch] = fast_sigmoid(s);
    }
}

extern "C" void kernel_launch(void* const* d_in, const int* in_sizes, int n_in,
                              void* d_out, int out_size) {
    const float* x  = (const float*)d_in[0];
    const float* Wx = (const float*)d_in[1];
    const float* Wh = (const float*)d_in[2];
    const float* b  = (const float*)d_in[3];
    const float* W2 = (const float*)d_in[4];
    const float* b2 = (const float*)d_in[5];
    const float* W3 = (const float*)d_in[6];
    const float* b3 = (const float*)d_in[7];
    const float* Wo = (const float*)d_in[8];
    const float* bo = (const float*)d_in[9];
    float* out = (float*)d_out;

    // 2048 batches, 1 warp each, 4 warps per block -> 512 blocks of 128 threads.
    lstm_fused_kernel<<<Bsz / 4, 128>>>(x, Wx, Wh, b, W2, b2, W3, b3, Wo, bo, out);
}